// round 6
// baseline (speedup 1.0000x reference)
#include <cuda_runtime.h>
#include <cuda_bf16.h>
#include <math.h>
#include <cstdint>

#define NN 100000
#define NE 625000
#define HH 128
#define H2 256
#define GG 64
#define NHOPS 5
#define EPSV 1e-5f

// ---------------- scratch (static device globals; no allocation) ----------------
static __device__ float  g_x  [(size_t)NN * HH];
static __device__ float  g_h  [(size_t)NN * HH];
static __device__ float  g_deg [NN];
static __device__ float  g_dinv[NN];
static __device__ float  g_vn  [GG * HH];
static __device__ float  g_vnh [GG * H2];
static __device__ float  g_pool[GG * HH];
static __device__ float  g_cnt [GG];
static __device__ double g_sum  [HH];
static __device__ double g_sumsq[HH];
static __device__ float  g_bnA[HH];
static __device__ float  g_bnC[HH];
// CSR
static __device__ int g_icnt[NN];
static __device__ int g_scan[NN];
static __device__ int g_bsum[512];
static __device__ int g_rowptr[NN + 1];
static __device__ int g_fill[NN];
static __device__ int g_ecol[NE];
// bf16 hi/lo split buffers (activations)
static __device__ __nv_bfloat16 g_ahi[(size_t)NN * HH];
static __device__ __nv_bfloat16 g_alo[(size_t)NN * HH];
static __device__ __nv_bfloat16 g_hhi[(size_t)NN * H2];
static __device__ __nv_bfloat16 g_hlo[(size_t)NN * H2];
// transposed + split weights: [N,K] row-major bf16
#define WTOT 475136
static __device__ __nv_bfloat16 g_whi[WTOT];
static __device__ __nv_bfloat16 g_wlo[WTOT];
#define OW_PRE1 0
#define OW_PRE2 32768
#define OW_CONV(i) (65536 + (i) * 16384)
#define OW_FFN1(i) (147456 + (i) * 32768)
#define OW_FFN2(i) (311296 + (i) * 32768)

__device__ __forceinline__ float gelu_f(float x) {
    return 0.5f * x * (1.0f + erff(x * 0.70710678118654752f));
}
__device__ __forceinline__ uint32_t smem_u32(const void* p) {
    uint32_t a;
    asm("{ .reg .u64 t; cvta.to.shared.u64 t, %1; cvt.u32.u64 %0, t; }" : "=r"(a) : "l"(p));
    return a;
}
__device__ __forceinline__ void ldsm4(uint32_t& r0, uint32_t& r1, uint32_t& r2, uint32_t& r3,
                                      uint32_t addr) {
    asm volatile("ldmatrix.sync.aligned.m8n8.x4.shared.b16 {%0,%1,%2,%3}, [%4];"
                 : "=r"(r0), "=r"(r1), "=r"(r2), "=r"(r3) : "r"(addr));
}
__device__ __forceinline__ void mma_bf16(float* c, uint32_t a0, uint32_t a1, uint32_t a2,
                                         uint32_t a3, uint32_t b0, uint32_t b1) {
    asm volatile("mma.sync.aligned.m16n8k16.row.col.f32.bf16.bf16.f32 "
                 "{%0,%1,%2,%3}, {%4,%5,%6,%7}, {%8,%9}, {%0,%1,%2,%3};"
                 : "+f"(c[0]), "+f"(c[1]), "+f"(c[2]), "+f"(c[3])
                 : "r"(a0), "r"(a1), "r"(a2), "r"(a3), "r"(b0), "r"(b1));
}
__device__ __forceinline__ void cp16(uint32_t dst, const void* src, int sz) {
    asm volatile("cp.async.cg.shared.global [%0], [%1], 16, %2;"
                 :: "r"(dst), "l"(src), "r"(sz) : "memory");
}
#define CP_COMMIT() asm volatile("cp.async.commit_group;" ::: "memory")
#define CP_WAIT(n)  asm volatile("cp.async.wait_group %0;" :: "n"(n) : "memory")

// ======================= HMMA bf16-split GEMM (double-buffered cp.async) =======================
#define KC 32
#define ROWB 80
#define BUFB (128 * ROWB)
#define STGB (4 * BUFB)
#define GSMEM (2 * STGB)

template <int FLAGS>
__global__ void __launch_bounds__(256, 2) mma_gemm(
    const __nv_bfloat16* __restrict__ Ahi, const __nv_bfloat16* __restrict__ Alo,
    const __nv_bfloat16* __restrict__ Bhi, const __nv_bfloat16* __restrict__ Blo,
    const float* __restrict__ bias, const float* __restrict__ Res,
    float* __restrict__ C, __nv_bfloat16* __restrict__ Chi, __nv_bfloat16* __restrict__ Clo,
    int M, int K, int Nc)
{
    extern __shared__ char sm[];
    uint32_t sb = smem_u32(sm);

    int t = threadIdx.x;
    int lid = t & 31, wid = t >> 5;
    int wm = wid & 3, wn = wid >> 2;
    int m0 = blockIdx.y * 128, n0 = blockIdx.x * 128;
    int nchunks = K / KC;

    float acc[2][8][4];
    #pragma unroll
    for (int i = 0; i < 2; i++)
        #pragma unroll
        for (int j = 0; j < 8; j++)
            #pragma unroll
            for (int k = 0; k < 4; k++) acc[i][j][k] = 0.f;

    auto issue = [&](int ch) {
        uint32_t st = sb + (uint32_t)(ch & 1) * STGB;
        int k0 = ch * KC;
        #pragma unroll
        for (int i = 0; i < 2; i++) {
            int c = t + i * 256;
            int r = c >> 2;
            int kcEl = (c & 3) * 8;
            uint32_t doff = (uint32_t)r * ROWB + (uint32_t)kcEl * 2;
            int ar = m0 + r;
            int okA = (ar < M) ? 16 : 0;
            int arc = okA ? ar : 0;
            cp16(st + doff,            Ahi + (size_t)arc * K + k0 + kcEl, okA);
            cp16(st + BUFB + doff,     Alo + (size_t)arc * K + k0 + kcEl, okA);
            int br = n0 + r;
            cp16(st + 2 * BUFB + doff, Bhi + (size_t)br * K + k0 + kcEl, 16);
            cp16(st + 3 * BUFB + doff, Blo + (size_t)br * K + k0 + kcEl, 16);
        }
        CP_COMMIT();
    };

    issue(0);
    for (int ch = 0; ch < nchunks; ch++) {
        if (ch + 1 < nchunks) { issue(ch + 1); CP_WAIT(1); }
        else                  { CP_WAIT(0); }
        __syncthreads();

        uint32_t st  = sb + (uint32_t)(ch & 1) * STGB;
        uint32_t sAh = st, sAl = st + BUFB, sBh = st + 2 * BUFB, sBl = st + 3 * BUFB;

        #pragma unroll
        for (int ks = 0; ks < 2; ks++) {
            int kk = ks * 16;
            uint32_t ah[2][4], al[2][4];
            #pragma unroll
            for (int mr = 0; mr < 2; mr++) {
                int row = wm * 32 + mr * 16 + (lid & 15);
                uint32_t off = (uint32_t)row * ROWB + ((uint32_t)kk + (lid >> 4) * 8) * 2;
                ldsm4(ah[mr][0], ah[mr][1], ah[mr][2], ah[mr][3], sAh + off);
                ldsm4(al[mr][0], al[mr][1], al[mr][2], al[mr][3], sAl + off);
            }
            #pragma unroll
            for (int np = 0; np < 4; np++) {
                int brow = wn * 64 + np * 16 + (lid & 7) + ((lid >> 4) & 1) * 8;
                uint32_t off = (uint32_t)brow * ROWB + ((uint32_t)kk + ((lid >> 3) & 1) * 8) * 2;
                uint32_t bh0, bh1, bh2, bh3, bl0, bl1, bl2, bl3;
                ldsm4(bh0, bh1, bh2, bh3, sBh + off);
                ldsm4(bl0, bl1, bl2, bl3, sBl + off);
                #pragma unroll
                for (int mr = 0; mr < 2; mr++) {
                    float* c0 = acc[mr][np * 2];
                    float* c1 = acc[mr][np * 2 + 1];
                    mma_bf16(c0, ah[mr][0], ah[mr][1], ah[mr][2], ah[mr][3], bh0, bh1);
                    mma_bf16(c0, ah[mr][0], ah[mr][1], ah[mr][2], ah[mr][3], bl0, bl1);
                    mma_bf16(c0, al[mr][0], al[mr][1], al[mr][2], al[mr][3], bh0, bh1);
                    mma_bf16(c1, ah[mr][0], ah[mr][1], ah[mr][2], ah[mr][3], bh2, bh3);
                    mma_bf16(c1, ah[mr][0], ah[mr][1], ah[mr][2], ah[mr][3], bl2, bl3);
                    mma_bf16(c1, al[mr][0], al[mr][1], al[mr][2], al[mr][3], bh2, bh3);
                }
            }
        }
        __syncthreads();
    }

    #pragma unroll
    for (int mr = 0; mr < 2; mr++) {
        int rbase = m0 + wm * 32 + mr * 16 + (lid >> 2);
        #pragma unroll
        for (int nc = 0; nc < 8; nc++) {
            int col = n0 + wn * 64 + nc * 8 + (lid & 3) * 2;
            #pragma unroll
            for (int e = 0; e < 4; e++) {
                int row = rbase + (e >> 1) * 8;
                int cc  = col + (e & 1);
                if (row >= M) continue;
                float v = acc[mr][nc][e];
                if (FLAGS & 1) v += bias[cc];
                if (FLAGS & 2) v = gelu_f(v);
                size_t gidx = (size_t)row * Nc + cc;
                if (FLAGS & 4) v += Res[gidx];
                if (!(FLAGS & 16)) C[gidx] = v;
                if (FLAGS & 8) {
                    __nv_bfloat16 h = __float2bfloat16(v);
                    Chi[gidx] = h;
                    Clo[gidx] = __float2bfloat16(v - __bfloat162float(h));
                }
            }
        }
    }
}

// ======================= fused weight prep: ALL weights, one launch =======================
__global__ void wprep_all_k(const float* __restrict__ pre_W1, const float* __restrict__ pre_W2,
                            const float* __restrict__ conv_W, const float* __restrict__ ffn_W1,
                            const float* __restrict__ ffn_W2) {
    int i = blockIdx.x * blockDim.x + threadIdx.x;
    if (i >= WTOT) return;
    const float* src; int K, Nc, off;
    if (i < 32768)       { src = pre_W1; K = HH; Nc = H2; off = i; }
    else if (i < 65536)  { src = pre_W2; K = H2; Nc = HH; off = i - 32768; }
    else if (i < 147456) { int l = (i - 65536) >> 14; src = conv_W + l * 16384;
                           K = HH; Nc = HH; off = (i - 65536) & 16383; }
    else if (i < 311296) { int l = (i - 147456) >> 15; src = ffn_W1 + (size_t)l * 32768;
                           K = HH; Nc = H2; off = (i - 147456) & 32767; }
    else                 { int l = (i - 311296) >> 15; src = ffn_W2 + (size_t)l * 32768;
                           K = H2; Nc = HH; off = (i - 311296) & 32767; }
    int n = off / K, k = off - n * K;
    float v = src[(size_t)k * Nc + n];
    __nv_bfloat16 h = __float2bfloat16(v);
    g_whi[i] = h;
    g_wlo[i] = __float2bfloat16(v - __bfloat162float(h));
}
__global__ void split_k(const float* __restrict__ X, __nv_bfloat16* __restrict__ hi,
                        __nv_bfloat16* __restrict__ lo, int n) {
    int i = blockIdx.x * blockDim.x + threadIdx.x;
    if (i >= n) return;
    float v = X[i];
    __nv_bfloat16 h = __float2bfloat16(v);
    hi[i] = h;
    lo[i] = __float2bfloat16(v - __bfloat162float(h));
}

// ---------------- small SIMT GEMM (final post-FFNN, G=64 rows) ----------------
template <int FLAGS>
__global__ void gemm64(const float* __restrict__ A, const float* __restrict__ W,
                       const float* __restrict__ bias, const float* __restrict__ Res,
                       float* __restrict__ C, int M, int K, int Nc)
{
    const int BM = 64, BN = 64, BK = 16;
    __shared__ float As[BK][BM + 4];
    __shared__ float Ws[BK][BN];
    int t  = threadIdx.x;
    int tx = t & 15, ty = t >> 4;
    int m0 = blockIdx.y * BM, n0 = blockIdx.x * BN;
    float acc[4][4] = {};
    int la_m = t >> 2, la_k = (t & 3) * 4;
    int lw_k = t >> 4, lw_n = (t & 15) * 4;
    for (int k0 = 0; k0 < K; k0 += BK) {
        int arow = m0 + la_m;
        if (arow < M) {
            float4 v = *reinterpret_cast<const float4*>(A + (size_t)arow * K + k0 + la_k);
            As[la_k + 0][la_m] = v.x; As[la_k + 1][la_m] = v.y;
            As[la_k + 2][la_m] = v.z; As[la_k + 3][la_m] = v.w;
        } else {
            As[la_k + 0][la_m] = 0.f; As[la_k + 1][la_m] = 0.f;
            As[la_k + 2][la_m] = 0.f; As[la_k + 3][la_m] = 0.f;
        }
        {
            float4 v = *reinterpret_cast<const float4*>(W + (size_t)(k0 + lw_k) * Nc + n0 + lw_n);
            *reinterpret_cast<float4*>(&Ws[lw_k][lw_n]) = v;
        }
        __syncthreads();
        #pragma unroll
        for (int kk = 0; kk < BK; kk++) {
            float4 ra = *reinterpret_cast<const float4*>(&As[kk][ty * 4]);
            float4 rb = *reinterpret_cast<const float4*>(&Ws[kk][tx * 4]);
            float a[4] = {ra.x, ra.y, ra.z, ra.w};
            float b[4] = {rb.x, rb.y, rb.z, rb.w};
            #pragma unroll
            for (int i = 0; i < 4; i++)
                #pragma unroll
                for (int j = 0; j < 4; j++)
                    acc[i][j] += a[i] * b[j];
        }
        __syncthreads();
    }
    #pragma unroll
    for (int i = 0; i < 4; i++) {
        int row = m0 + ty * 4 + i;
        if (row >= M) continue;
        #pragma unroll
        for (int j = 0; j < 4; j++) {
            int col = n0 + tx * 4 + j;
            float v = acc[i][j];
            if (FLAGS & 1) v += bias[col];
            if (FLAGS & 2) v = gelu_f(v);
            if (FLAGS & 4) v += Res[(size_t)row * Nc + col];
            C[(size_t)row * Nc + col] = v;
        }
    }
}

// ---------------- graph prep ----------------
__global__ void deg_init_k() {
    int i = blockIdx.x * blockDim.x + threadIdx.x;
    if (i < NN) { g_deg[i] = 1.0f; g_icnt[i] = 0; }
    if (i < GG) g_cnt[i] = 0.0f;
}
__global__ void deg_edge_k(const int* __restrict__ dst) {
    int e = blockIdx.x * blockDim.x + threadIdx.x;
    if (e < NE) {
        int d = dst[e];
        atomicAdd(&g_deg[d], 1.0f);
        atomicAdd(&g_icnt[d], 1);
    }
}
__global__ void dinv_cnt_k(const int* __restrict__ batch) {
    int i = blockIdx.x * blockDim.x + threadIdx.x;
    if (i < NN) {
        g_dinv[i] = rsqrtf(g_deg[i]);
        atomicAdd(&g_cnt[batch[i]], 1.0f);
    }
}
// ---- CSR scan ----
__global__ void scan1_k() {
    __shared__ int sh[256];
    int i = blockIdx.x * 256 + threadIdx.x;
    int v = (i < NN) ? g_icnt[i] : 0;
    sh[threadIdx.x] = v;
    __syncthreads();
    for (int o = 1; o < 256; o <<= 1) {
        int tv = (threadIdx.x >= o) ? sh[threadIdx.x - o] : 0;
        __syncthreads();
        sh[threadIdx.x] += tv;
        __syncthreads();
    }
    if (i < NN) g_scan[i] = sh[threadIdx.x] - v;
    if (threadIdx.x == 255) g_bsum[blockIdx.x] = sh[255];
}
__global__ void scan2_k(int nb) {
    __shared__ int sh[512];
    int t = threadIdx.x;
    int v = (t < nb) ? g_bsum[t] : 0;
    sh[t] = v;
    __syncthreads();
    for (int o = 1; o < 512; o <<= 1) {
        int tv = (t >= o) ? sh[t - o] : 0;
        __syncthreads();
        sh[t] += tv;
        __syncthreads();
    }
    if (t < nb) g_bsum[t] = sh[t] - v;
}
__global__ void scan3_k() {
    int i = blockIdx.x * blockDim.x + threadIdx.x;
    if (i < NN) {
        int rp = g_scan[i] + g_bsum[i >> 8];
        g_rowptr[i] = rp;
        g_fill[i] = rp;
    }
    if (i == 0) g_rowptr[NN] = NE;
}
__global__ void scatter_k(const int* __restrict__ src, const int* __restrict__ dst) {
    int e = blockIdx.x * blockDim.x + threadIdx.x;
    if (e < NE) {
        int pos = atomicAdd(&g_fill[dst[e]], 1);
        g_ecol[pos] = src[e];
    }
}

// ---------------- per-hop elementwise ----------------
__global__ void vn_init_k(const float* __restrict__ vn_emb) {
    int i = blockIdx.x * blockDim.x + threadIdx.x;
    if (i < GG * HH) g_vn[i] = vn_emb[i & (HH - 1)];
}
// x += vn[batch]; write split; block 0 zeros BN accumulators
__global__ void addvn_split_k(const int* __restrict__ batch) {
    int idx = blockIdx.x * blockDim.x + threadIdx.x;
    if (blockIdx.x == 0 && threadIdx.x < HH) {
        g_sum[threadIdx.x] = 0.0; g_sumsq[threadIdx.x] = 0.0;
    }
    if (idx < NN * HH) {
        int r = idx >> 7, f = idx & 127;
        float v = g_x[idx] + g_vn[batch[r] * HH + f];
        g_x[idx] = v;
        __nv_bfloat16 h = __float2bfloat16(v);
        g_ahi[idx] = h;
        g_alo[idx] = __float2bfloat16(v - __bfloat162float(h));
    }
}
// CSR gather + conv bias + residual + fp64 BN stats
__global__ void gcn_gather_bn_k(const float* __restrict__ bias) {
    int gtid = blockIdx.x * blockDim.x + threadIdx.x;
    int warp = gtid >> 5, lane = gtid & 31;
    int nw = (gridDim.x * blockDim.x) >> 5;
    float4 b4 = *reinterpret_cast<const float4*>(bias + lane * 4);
    double s0 = 0, s1 = 0, s2 = 0, s3 = 0, q0 = 0, q1 = 0, q2 = 0, q3 = 0;
    for (int n = warp; n < NN; n += nw) {
        float di = g_dinv[n];
        size_t rb = (size_t)n * HH + lane * 4;
        float4 hv = *reinterpret_cast<const float4*>(g_h + rb);
        float sl = di * di;
        float ax = hv.x * sl, ay = hv.y * sl, az = hv.z * sl, aw = hv.w * sl;
        int e0 = g_rowptr[n], e1 = g_rowptr[n + 1];
        #pragma unroll 4
        for (int e = e0; e < e1; e++) {
            int sI = g_ecol[e];
            float nrm = g_dinv[sI] * di;
            float4 v = *reinterpret_cast<const float4*>(g_h + (size_t)sI * HH + lane * 4);
            ax += v.x * nrm; ay += v.y * nrm; az += v.z * nrm; aw += v.w * nrm;
        }
        float4 xv = *reinterpret_cast<const float4*>(g_x + rb);
        float t0 = ax + b4.x + xv.x;
        float t1 = ay + b4.y + xv.y;
        float t2 = az + b4.z + xv.z;
        float t3 = aw + b4.w + xv.w;
        *reinterpret_cast<float4*>(g_x + rb) = make_float4(t0, t1, t2, t3);
        s0 += t0; s1 += t1; s2 += t2; s3 += t3;
        q0 += (double)t0 * t0; q1 += (double)t1 * t1;
        q2 += (double)t2 * t2; q3 += (double)t3 * t3;
    }
    atomicAdd(&g_sum[lane * 4 + 0], s0); atomicAdd(&g_sumsq[lane * 4 + 0], q0);
    atomicAdd(&g_sum[lane * 4 + 1], s1); atomicAdd(&g_sumsq[lane * 4 + 1], q1);
    atomicAdd(&g_sum[lane * 4 + 2], s2); atomicAdd(&g_sumsq[lane * 4 + 2], q2);
    atomicAdd(&g_sum[lane * 4 + 3], s3); atomicAdd(&g_sumsq[lane * 4 + 3], q3);
}
__global__ void bn_final_k(const float* __restrict__ gam, const float* __restrict__ bet) {
    int f = threadIdx.x;
    double mean = g_sum[f] / (double)NN;
    double var  = g_sumsq[f] / (double)NN - mean * mean;
    float a = gam[f] * rsqrtf((float)var + EPSV);
    g_bnA[f] = a;
    g_bnC[f] = bet[f] - (float)mean * a;
}
// BN apply + split; block 0 zeros g_pool for the upcoming pooling
__global__ void bn_apply_split_k() {
    int idx = blockIdx.x * blockDim.x + threadIdx.x;
    if (blockIdx.x == 0) {
        for (int p = threadIdx.x; p < GG * HH; p += 256) g_pool[p] = 0.0f;
    }
    if (idx < NN * HH) {
        int f = idx & 127;
        float v = g_x[idx] * g_bnA[f] + g_bnC[f];
        g_x[idx] = v;
        __nv_bfloat16 h = __float2bfloat16(v);
        g_ahi[idx] = h;
        g_alo[idx] = __float2bfloat16(v - __bfloat162float(h));
    }
}

// ---------------- pooling + fused vn-MLP ----------------
#define PROWS 128
__global__ void pool_k(const float* __restrict__ X, const int* __restrict__ batch) {
    int f = threadIdx.x;
    int r0 = blockIdx.x * PROWS;
    int r1 = min(r0 + PROWS, NN);
    float acc = 0.0f;
    int cur = batch[r0];
    for (int r = r0; r < r1; r++) {
        int gidx = batch[r];
        if (gidx != cur) {
            atomicAdd(&g_pool[cur * HH + f], acc);
            acc = 0.0f; cur = gidx;
        }
        acc += X[(size_t)r * HH + f];
    }
    atomicAdd(&g_pool[cur * HH + f], acc);
}
// vnh[g][f] = gelu(BN( sum_k (vn[g][k] + pool[g][k]/cnt[g]) * W1[k][f] + b1[f] ))
__global__ void vn_mlp1_k(const float* __restrict__ W1, const float* __restrict__ b1,
                          const float* __restrict__ g1, const float* __restrict__ be1) {
    int f = blockIdx.x;           // 0..H2-1
    int g = threadIdx.x;          // 0..63
    float ic = 1.0f / fmaxf(g_cnt[g], 1.0f);
    float acc = b1[f];
    #pragma unroll 4
    for (int k = 0; k < HH; k++) {
        float vnk = g_vn[g * HH + k] + g_pool[g * HH + k] * ic;
        acc += vnk * W1[k * H2 + f];
    }
    __shared__ float sh[64], sh2[64];
    sh[g] = acc; sh2[g] = acc * acc;
    __syncthreads();
    for (int o = 32; o > 0; o >>= 1) {
        if (g < o) { sh[g] += sh[g + o]; sh2[g] += sh2[g + o]; }
        __syncthreads();
    }
    float mean = sh[0] * (1.0f / 64.0f);
    float var  = sh2[0] * (1.0f / 64.0f) - mean * mean;
    float a = g1[f] * rsqrtf(var + EPSV);
    float c = be1[f] - mean * a;
    g_vnh[g * H2 + f] = gelu_f(acc * a + c);
}
// vn[g][f] = gelu(BN( sum_k vnh[g][k] * W2[k][f] + b2[f] ))
__global__ void vn_mlp2_k(const float* __restrict__ W2, const float* __restrict__ b2,
                          const float* __restrict__ g2, const float* __restrict__ be2) {
    int f = blockIdx.x;           // 0..HH-1
    int g = threadIdx.x;          // 0..63
    float acc = b2[f];
    #pragma unroll 4
    for (int k = 0; k < H2; k++)
        acc += g_vnh[g * H2 + k] * W2[k * HH + f];
    __shared__ float sh[64], sh2[64];
    sh[g] = acc; sh2[g] = acc * acc;
    __syncthreads();
    for (int o = 32; o > 0; o >>= 1) {
        if (g < o) { sh[g] += sh[g + o]; sh2[g] += sh2[g + o]; }
        __syncthreads();
    }
    float mean = sh[0] * (1.0f / 64.0f);
    float var  = sh2[0] * (1.0f / 64.0f) - mean * mean;
    float a = g2[f] * rsqrtf(var + EPSV);
    float c = be2[f] - mean * a;
    g_vn[g * HH + f] = gelu_f(acc * a + c);
}

// ---------------- host ----------------
extern "C" void kernel_launch(void* const* d_in, const int* in_sizes, int n_in,
                              void* d_out, int out_size)
{
    const float* x_in   = (const float*)d_in[0];
    const int*   ei     = (const int*)  d_in[1];
    const int*   batch  = (const int*)  d_in[2];
    const float* pre_W1 = (const float*)d_in[3];
    const float* pre_b1 = (const float*)d_in[4];
    const float* pre_W2 = (const float*)d_in[5];
    const float* pre_b2 = (const float*)d_in[6];
    const float* conv_W = (const float*)d_in[7];
    const float* conv_b = (const float*)d_in[8];
    const float* bn_g   = (const float*)d_in[9];
    const float* bn_b   = (const float*)d_in[10];
    const float* ffn_W1 = (const float*)d_in[11];
    const float* ffn_b1 = (const float*)d_in[12];
    const float* ffn_W2 = (const float*)d_in[13];
    const float* ffn_b2 = (const float*)d_in[14];
    const float* vn_W1  = (const float*)d_in[15];
    const float* vn_b1  = (const float*)d_in[16];
    const float* vn_g1  = (const float*)d_in[17];
    const float* vn_be1 = (const float*)d_in[18];
    const float* vn_W2  = (const float*)d_in[19];
    const float* vn_b2  = (const float*)d_in[20];
    const float* vn_g2  = (const float*)d_in[21];
    const float* vn_be2 = (const float*)d_in[22];
    const float* vn_emb = (const float*)d_in[23];
    const float* post_W1= (const float*)d_in[24];
    const float* post_b1= (const float*)d_in[25];
    const float* post_W2= (const float*)d_in[26];
    const float* post_b2= (const float*)d_in[27];
    float* out = (float*)d_out;

    const int* src = ei;
    const int* dst = ei + NE;

    float *px, *ph, *ppool, *pvnh;
    __nv_bfloat16 *pahi, *palo, *phhi, *phlo, *pwhi, *pwlo;
    cudaGetSymbolAddress((void**)&px,   g_x);
    cudaGetSymbolAddress((void**)&ph,   g_h);
    cudaGetSymbolAddress((void**)&ppool,g_pool);
    cudaGetSymbolAddress((void**)&pvnh, g_vnh);
    cudaGetSymbolAddress((void**)&pahi, g_ahi);
    cudaGetSymbolAddress((void**)&palo, g_alo);
    cudaGetSymbolAddress((void**)&phhi, g_hhi);
    cudaGetSymbolAddress((void**)&phlo, g_hlo);
    cudaGetSymbolAddress((void**)&pwhi, g_whi);
    cudaGetSymbolAddress((void**)&pwlo, g_wlo);

    cudaFuncSetAttribute(mma_gemm<27>, cudaFuncAttributeMaxDynamicSharedMemorySize, GSMEM);
    cudaFuncSetAttribute(mma_gemm<3>,  cudaFuncAttributeMaxDynamicSharedMemorySize, GSMEM);
    cudaFuncSetAttribute(mma_gemm<0>,  cudaFuncAttributeMaxDynamicSharedMemorySize, GSMEM);
    cudaFuncSetAttribute(mma_gemm<7>,  cudaFuncAttributeMaxDynamicSharedMemorySize, GSMEM);

    const int EW = NN * HH;
    dim3 blk(256);
    int gEW = (EW + 255) / 256;
    const int MT = (NN + 127) / 128;   // 782
    const int NB = (NN + 255) / 256;   // 391

    // ---- launches 1-5 (profiler skips these), #6 = mma_gemm<27> (profiled) ----
    wprep_all_k<<<(WTOT + 255) / 256, blk>>>(pre_W1, pre_W2, conv_W, ffn_W1, ffn_W2); // 1
    split_k<<<gEW, blk>>>(x_in, pahi, palo, EW);                                      // 2
    deg_init_k<<<NB, blk>>>();                                                        // 3
    deg_edge_k<<<(NE + 255) / 256, blk>>>(dst);                                       // 4
    dinv_cnt_k<<<NB, blk>>>(batch);                                                   // 5
    mma_gemm<27><<<dim3(2, MT), 256, GSMEM>>>(pahi, palo, pwhi + OW_PRE1, pwlo + OW_PRE1,
        pre_b1, nullptr, nullptr, phhi, phlo, NN, HH, H2);                            // 6 <- ncu
    // ---- rest of CSR prep ----
    scan1_k<<<NB, blk>>>();
    scan2_k<<<1, 512>>>(NB);
    scan3_k<<<NB, blk>>>();
    scatter_k<<<(NE + 255) / 256, blk>>>(src, dst);
    // ---- pre-FFNN part 2 ----
    mma_gemm<3><<<dim3(1, MT), 256, GSMEM>>>(phhi, phlo, pwhi + OW_PRE2, pwlo + OW_PRE2,
        pre_b2, nullptr, px, nullptr, nullptr, NN, H2, HH);
    vn_init_k<<<(GG * HH + 255) / 256, blk>>>(vn_emb);

    for (int i = 0; i < NHOPS; i++) {
        addvn_split_k<<<gEW, blk>>>(batch);
        mma_gemm<0><<<dim3(1, MT), 256, GSMEM>>>(pahi, palo, pwhi + OW_CONV(i), pwlo + OW_CONV(i),
            nullptr, nullptr, ph, nullptr, nullptr, NN, HH, HH);
        gcn_gather_bn_k<<<256, 256>>>(conv_b + (size_t)i * HH);
        bn_final_k<<<1, HH>>>(bn_g + (size_t)i * HH, bn_b + (size_t)i * HH);
        bn_apply_split_k<<<gEW, blk>>>();
        mma_gemm<27><<<dim3(2, MT), 256, GSMEM>>>(pahi, palo, pwhi + OW_FFN1(i), pwlo + OW_FFN1(i),
            ffn_b1 + (size_t)i * H2, nullptr, nullptr, phhi, phlo, NN, HH, H2);
        mma_gemm<7><<<dim3(1, MT), 256, GSMEM>>>(phhi, phlo, pwhi + OW_FFN2(i), pwlo + OW_FFN2(i),
            ffn_b2 + (size_t)i * HH, px, px, nullptr, nullptr, NN, H2, HH);
        if (i < NHOPS - 1) {
            pool_k<<<(NN + PROWS - 1) / PROWS, HH>>>(px, batch);
            vn_mlp1_k<<<H2, GG>>>(vn_W1 + (size_t)i * HH * H2, vn_b1 + (size_t)i * H2,
                                  vn_g1 + (size_t)i * H2, vn_be1 + (size_t)i * H2);
            vn_mlp2_k<<<HH, GG>>>(vn_W2 + (size_t)i * H2 * HH, vn_b2 + (size_t)i * HH,
                                  vn_g2 + (size_t)i * HH, vn_be2 + (size_t)i * HH);
        }
    }

    // ---- final pool + post-FFNN ----
    pool_k<<<(NN + PROWS - 1) / PROWS, HH>>>(px, batch);
    dim3 gp1(H2 / 64, 1);
    gemm64<3><<<gp1, blk>>>(ppool, post_W1, post_b1, nullptr, pvnh, GG, HH, H2);
    dim3 gp2(HH / 64, 1);
    gemm64<3><<<gp2, blk>>>(pvnh, post_W2, post_b2, nullptr, out, GG, H2, HH);
}

// round 7
// speedup vs baseline: 1.0685x; 1.0685x over previous
#include <cuda_runtime.h>
#include <cuda_fp16.h>
#include <math.h>
#include <cstdint>

#define NN 100000
#define NE 625000
#define HH 128
#define H2 256
#define GG 64
#define NHOPS 5
#define EPSV 1e-5f

// ---------------- scratch (static device globals; no allocation) ----------------
static __device__ float  g_x  [(size_t)NN * HH];
static __device__ float  g_h  [(size_t)NN * HH];
static __device__ float  g_deg [NN];
static __device__ float  g_dinv[NN];
static __device__ float  g_vn  [GG * HH];
static __device__ float  g_vnh [GG * H2];
static __device__ float  g_pool[GG * HH];
static __device__ float  g_cnt [GG];
static __device__ double g_sum  [HH];
static __device__ double g_sumsq[HH];
static __device__ float  g_bnA[HH];
static __device__ float  g_bnC[HH];
// CSR
static __device__ int g_icnt[NN];
static __device__ int g_scan[NN];
static __device__ int g_bsum[512];
static __device__ int g_rowptr[NN + 1];
static __device__ int g_fill[NN];
static __device__ int g_ecol[NE];
// fp16 hi/lo split buffers (activations); weights single fp16
static __device__ __half g_ahi[(size_t)NN * HH];
static __device__ __half g_alo[(size_t)NN * HH];
static __device__ __half g_hhi[(size_t)NN * H2];
static __device__ __half g_hlo[(size_t)NN * H2];
#define WTOT 475136
static __device__ __half g_wh[WTOT];
#define OW_PRE1 0
#define OW_PRE2 32768
#define OW_CONV(i) (65536 + (i) * 16384)
#define OW_FFN1(i) (147456 + (i) * 32768)
#define OW_FFN2(i) (311296 + (i) * 32768)

__device__ __forceinline__ float gelu_f(float x) {
    return 0.5f * x * (1.0f + erff(x * 0.70710678118654752f));
}
__device__ __forceinline__ uint32_t smem_u32(const void* p) {
    uint32_t a;
    asm("{ .reg .u64 t; cvta.to.shared.u64 t, %1; cvt.u32.u64 %0, t; }" : "=r"(a) : "l"(p));
    return a;
}
__device__ __forceinline__ void ldsm4(uint32_t& r0, uint32_t& r1, uint32_t& r2, uint32_t& r3,
                                      uint32_t addr) {
    asm volatile("ldmatrix.sync.aligned.m8n8.x4.shared.b16 {%0,%1,%2,%3}, [%4];"
                 : "=r"(r0), "=r"(r1), "=r"(r2), "=r"(r3) : "r"(addr));
}
__device__ __forceinline__ void mma_f16(float* c, uint32_t a0, uint32_t a1, uint32_t a2,
                                        uint32_t a3, uint32_t b0, uint32_t b1) {
    asm volatile("mma.sync.aligned.m16n8k16.row.col.f32.f16.f16.f32 "
                 "{%0,%1,%2,%3}, {%4,%5,%6,%7}, {%8,%9}, {%0,%1,%2,%3};"
                 : "+f"(c[0]), "+f"(c[1]), "+f"(c[2]), "+f"(c[3])
                 : "r"(a0), "r"(a1), "r"(a2), "r"(a3), "r"(b0), "r"(b1));
}
__device__ __forceinline__ void cp16(uint32_t dst, const void* src, int sz) {
    asm volatile("cp.async.cg.shared.global [%0], [%1], 16, %2;"
                 :: "r"(dst), "l"(src), "r"(sz) : "memory");
}
#define CP_COMMIT() asm volatile("cp.async.commit_group;" ::: "memory")
#define CP_WAIT(n)  asm volatile("cp.async.wait_group %0;" :: "n"(n) : "memory")

// ======== fp16-split GEMM: C = epi(A@Wt^T), A = ah+al (fp16 x2), Wt single fp16 ========
// CTA 128x128, 256 thr (8 warps = 4M x 2N), 3-stage cp.async pipeline, 2 CTAs/SM.
// FLAGS: 1=+bias 2=gelu 4=+Res 8=write hi/lo split 16=skip fp32 C store
#define KC 32
#define ROWB 80
#define BUFB (128 * ROWB)       // 10240
#define STGB (3 * BUFB)         // 30720 per stage (Ah, Al, B)
#define GSMEM (3 * STGB)        // 92160 (3 stages)

template <int FLAGS>
__global__ void __launch_bounds__(256, 2) mma_gemm(
    const __half* __restrict__ Ahi, const __half* __restrict__ Alo,
    const __half* __restrict__ B,
    const float* __restrict__ bias, const float* __restrict__ Res,
    float* __restrict__ C, __half* __restrict__ Chi, __half* __restrict__ Clo,
    int M, int K, int Nc)
{
    extern __shared__ char sm[];
    uint32_t sb = smem_u32(sm);

    int t = threadIdx.x;
    int lid = t & 31, wid = t >> 5;
    int wm = wid & 3, wn = wid >> 2;
    int m0 = blockIdx.y * 128, n0 = blockIdx.x * 128;
    int nchunks = K / KC;

    float acc[2][8][4];
    #pragma unroll
    for (int i = 0; i < 2; i++)
        #pragma unroll
        for (int j = 0; j < 8; j++)
            #pragma unroll
            for (int k = 0; k < 4; k++) acc[i][j][k] = 0.f;

    auto issue = [&](int ch) {
        uint32_t st = sb + (uint32_t)(ch % 3) * STGB;
        int k0 = ch * KC;
        #pragma unroll
        for (int i = 0; i < 2; i++) {
            int c = t + i * 256;
            int r = c >> 2;
            int kcEl = (c & 3) * 8;
            uint32_t doff = (uint32_t)r * ROWB + (uint32_t)kcEl * 2;
            int ar = m0 + r;
            int okA = (ar < M) ? 16 : 0;
            int arc = okA ? ar : 0;
            cp16(st + doff,            Ahi + (size_t)arc * K + k0 + kcEl, okA);
            cp16(st + BUFB + doff,     Alo + (size_t)arc * K + k0 + kcEl, okA);
            int br = n0 + r;
            cp16(st + 2 * BUFB + doff, B + (size_t)br * K + k0 + kcEl, 16);
        }
        CP_COMMIT();
    };

    issue(0);
    if (nchunks > 1) issue(1);
    for (int ch = 0; ch < nchunks; ch++) {
        if (ch + 2 < nchunks)      { issue(ch + 2); CP_WAIT(2); }
        else if (ch + 1 < nchunks) { CP_WAIT(1); }
        else                       { CP_WAIT(0); }
        __syncthreads();

        uint32_t st = sb + (uint32_t)(ch % 3) * STGB;
        uint32_t sAh = st, sAl = st + BUFB, sB = st + 2 * BUFB;

        #pragma unroll
        for (int ks = 0; ks < 2; ks++) {
            int kk = ks * 16;
            uint32_t ah[2][4], al[2][4];
            #pragma unroll
            for (int mr = 0; mr < 2; mr++) {
                int row = wm * 32 + mr * 16 + (lid & 15);
                uint32_t off = (uint32_t)row * ROWB + ((uint32_t)kk + (lid >> 4) * 8) * 2;
                ldsm4(ah[mr][0], ah[mr][1], ah[mr][2], ah[mr][3], sAh + off);
                ldsm4(al[mr][0], al[mr][1], al[mr][2], al[mr][3], sAl + off);
            }
            #pragma unroll
            for (int np = 0; np < 4; np++) {
                int brow = wn * 64 + np * 16 + (lid & 7) + ((lid >> 4) & 1) * 8;
                uint32_t off = (uint32_t)brow * ROWB + ((uint32_t)kk + ((lid >> 3) & 1) * 8) * 2;
                uint32_t b0, b1, b2, b3;
                ldsm4(b0, b1, b2, b3, sB + off);
                #pragma unroll
                for (int mr = 0; mr < 2; mr++) {
                    float* c0 = acc[mr][np * 2];
                    float* c1 = acc[mr][np * 2 + 1];
                    mma_f16(c0, ah[mr][0], ah[mr][1], ah[mr][2], ah[mr][3], b0, b1);
                    mma_f16(c0, al[mr][0], al[mr][1], al[mr][2], al[mr][3], b0, b1);
                    mma_f16(c1, ah[mr][0], ah[mr][1], ah[mr][2], ah[mr][3], b2, b3);
                    mma_f16(c1, al[mr][0], al[mr][1], al[mr][2], al[mr][3], b2, b3);
                }
            }
        }
        __syncthreads();
    }

    #pragma unroll
    for (int mr = 0; mr < 2; mr++) {
        int rbase = m0 + wm * 32 + mr * 16 + (lid >> 2);
        #pragma unroll
        for (int nc = 0; nc < 8; nc++) {
            int col = n0 + wn * 64 + nc * 8 + (lid & 3) * 2;
            #pragma unroll
            for (int e = 0; e < 4; e++) {
                int row = rbase + (e >> 1) * 8;
                int cc  = col + (e & 1);
                if (row >= M) continue;
                float v = acc[mr][nc][e];
                if (FLAGS & 1) v += bias[cc];
                if (FLAGS & 2) v = gelu_f(v);
                size_t gidx = (size_t)row * Nc + cc;
                if (FLAGS & 4) v += Res[gidx];
                if (!(FLAGS & 16)) C[gidx] = v;
                if (FLAGS & 8) {
                    __half h = __float2half_rn(v);
                    Chi[gidx] = h;
                    Clo[gidx] = __float2half_rn(v - __half2float(h));
                }
            }
        }
    }
}

// ======================= fused weight prep (single fp16, transposed) =======================
__global__ void wprep_all_k(const float* __restrict__ pre_W1, const float* __restrict__ pre_W2,
                            const float* __restrict__ conv_W, const float* __restrict__ ffn_W1,
                            const float* __restrict__ ffn_W2) {
    int i = blockIdx.x * blockDim.x + threadIdx.x;
    if (i >= WTOT) return;
    const float* src; int K, Nc, off;
    if (i < 32768)       { src = pre_W1; K = HH; Nc = H2; off = i; }
    else if (i < 65536)  { src = pre_W2; K = H2; Nc = HH; off = i - 32768; }
    else if (i < 147456) { int l = (i - 65536) >> 14; src = conv_W + l * 16384;
                           K = HH; Nc = HH; off = (i - 65536) & 16383; }
    else if (i < 311296) { int l = (i - 147456) >> 15; src = ffn_W1 + (size_t)l * 32768;
                           K = HH; Nc = H2; off = (i - 147456) & 32767; }
    else                 { int l = (i - 311296) >> 15; src = ffn_W2 + (size_t)l * 32768;
                           K = H2; Nc = HH; off = (i - 311296) & 32767; }
    int n = off / K, k = off - n * K;
    g_wh[i] = __float2half_rn(src[(size_t)k * Nc + n]);
}
__global__ void split_k(const float* __restrict__ X, __half* __restrict__ hi,
                        __half* __restrict__ lo, int n) {
    int i = blockIdx.x * blockDim.x + threadIdx.x;
    if (i >= n) return;
    float v = X[i];
    __half h = __float2half_rn(v);
    hi[i] = h;
    lo[i] = __float2half_rn(v - __half2float(h));
}

// ---------------- small SIMT GEMM (final post-FFNN, G=64 rows) ----------------
template <int FLAGS>
__global__ void gemm64(const float* __restrict__ A, const float* __restrict__ W,
                       const float* __restrict__ bias, const float* __restrict__ Res,
                       float* __restrict__ C, int M, int K, int Nc)
{
    const int BM = 64, BN = 64, BK = 16;
    __shared__ float As[BK][BM + 4];
    __shared__ float Ws[BK][BN];
    int t  = threadIdx.x;
    int tx = t & 15, ty = t >> 4;
    int m0 = blockIdx.y * BM, n0 = blockIdx.x * BN;
    float acc[4][4] = {};
    int la_m = t >> 2, la_k = (t & 3) * 4;
    int lw_k = t >> 4, lw_n = (t & 15) * 4;
    for (int k0 = 0; k0 < K; k0 += BK) {
        int arow = m0 + la_m;
        if (arow < M) {
            float4 v = *reinterpret_cast<const float4*>(A + (size_t)arow * K + k0 + la_k);
            As[la_k + 0][la_m] = v.x; As[la_k + 1][la_m] = v.y;
            As[la_k + 2][la_m] = v.z; As[la_k + 3][la_m] = v.w;
        } else {
            As[la_k + 0][la_m] = 0.f; As[la_k + 1][la_m] = 0.f;
            As[la_k + 2][la_m] = 0.f; As[la_k + 3][la_m] = 0.f;
        }
        {
            float4 v = *reinterpret_cast<const float4*>(W + (size_t)(k0 + lw_k) * Nc + n0 + lw_n);
            *reinterpret_cast<float4*>(&Ws[lw_k][lw_n]) = v;
        }
        __syncthreads();
        #pragma unroll
        for (int kk = 0; kk < BK; kk++) {
            float4 ra = *reinterpret_cast<const float4*>(&As[kk][ty * 4]);
            float4 rb = *reinterpret_cast<const float4*>(&Ws[kk][tx * 4]);
            float a[4] = {ra.x, ra.y, ra.z, ra.w};
            float b[4] = {rb.x, rb.y, rb.z, rb.w};
            #pragma unroll
            for (int i = 0; i < 4; i++)
                #pragma unroll
                for (int j = 0; j < 4; j++)
                    acc[i][j] += a[i] * b[j];
        }
        __syncthreads();
    }
    #pragma unroll
    for (int i = 0; i < 4; i++) {
        int row = m0 + ty * 4 + i;
        if (row >= M) continue;
        #pragma unroll
        for (int j = 0; j < 4; j++) {
            int col = n0 + tx * 4 + j;
            float v = acc[i][j];
            if (FLAGS & 1) v += bias[col];
            if (FLAGS & 2) v = gelu_f(v);
            if (FLAGS & 4) v += Res[(size_t)row * Nc + col];
            C[(size_t)row * Nc + col] = v;
        }
    }
}

// ---------------- graph prep ----------------
__global__ void deg_init_k() {
    int i = blockIdx.x * blockDim.x + threadIdx.x;
    if (i < NN) { g_deg[i] = 1.0f; g_icnt[i] = 0; }
    if (i < GG) g_cnt[i] = 0.0f;
}
__global__ void deg_edge_k(const int* __restrict__ dst) {
    int e = blockIdx.x * blockDim.x + threadIdx.x;
    if (e < NE) {
        int d = dst[e];
        atomicAdd(&g_deg[d], 1.0f);
        atomicAdd(&g_icnt[d], 1);
    }
}
__global__ void dinv_cnt_k(const int* __restrict__ batch) {
    int i = blockIdx.x * blockDim.x + threadIdx.x;
    if (i < NN) {
        g_dinv[i] = rsqrtf(g_deg[i]);
        atomicAdd(&g_cnt[batch[i]], 1.0f);
    }
}
// ---- CSR scan ----
__global__ void scan1_k() {
    __shared__ int sh[256];
    int i = blockIdx.x * 256 + threadIdx.x;
    int v = (i < NN) ? g_icnt[i] : 0;
    sh[threadIdx.x] = v;
    __syncthreads();
    for (int o = 1; o < 256; o <<= 1) {
        int tv = (threadIdx.x >= o) ? sh[threadIdx.x - o] : 0;
        __syncthreads();
        sh[threadIdx.x] += tv;
        __syncthreads();
    }
    if (i < NN) g_scan[i] = sh[threadIdx.x] - v;
    if (threadIdx.x == 255) g_bsum[blockIdx.x] = sh[255];
}
__global__ void scan2_k(int nb) {
    __shared__ int sh[512];
    int t = threadIdx.x;
    int v = (t < nb) ? g_bsum[t] : 0;
    sh[t] = v;
    __syncthreads();
    for (int o = 1; o < 512; o <<= 1) {
        int tv = (t >= o) ? sh[t - o] : 0;
        __syncthreads();
        sh[t] += tv;
        __syncthreads();
    }
    if (t < nb) g_bsum[t] = sh[t] - v;
}
__global__ void scan3_k() {
    int i = blockIdx.x * blockDim.x + threadIdx.x;
    if (i < NN) {
        int rp = g_scan[i] + g_bsum[i >> 8];
        g_rowptr[i] = rp;
        g_fill[i] = rp;
    }
    if (i == 0) g_rowptr[NN] = NE;
}
__global__ void scatter_k(const int* __restrict__ src, const int* __restrict__ dst) {
    int e = blockIdx.x * blockDim.x + threadIdx.x;
    if (e < NE) {
        int pos = atomicAdd(&g_fill[dst[e]], 1);
        g_ecol[pos] = src[e];
    }
}

// ---------------- per-hop elementwise ----------------
__global__ void vn_init_k(const float* __restrict__ vn_emb) {
    int i = blockIdx.x * blockDim.x + threadIdx.x;
    if (i < GG * HH) g_vn[i] = vn_emb[i & (HH - 1)];
}
__global__ void addvn_split_k(const int* __restrict__ batch) {
    int idx = blockIdx.x * blockDim.x + threadIdx.x;
    if (blockIdx.x == 0 && threadIdx.x < HH) {
        g_sum[threadIdx.x] = 0.0; g_sumsq[threadIdx.x] = 0.0;
    }
    if (idx < NN * HH) {
        int r = idx >> 7, f = idx & 127;
        float v = g_x[idx] + g_vn[batch[r] * HH + f];
        g_x[idx] = v;
        __half h = __float2half_rn(v);
        g_ahi[idx] = h;
        g_alo[idx] = __float2half_rn(v - __half2float(h));
    }
}
// CSR gather + conv bias + residual + fp64 BN stats
__global__ void gcn_gather_bn_k(const float* __restrict__ bias) {
    int gtid = blockIdx.x * blockDim.x + threadIdx.x;
    int warp = gtid >> 5, lane = gtid & 31;
    int nw = (gridDim.x * blockDim.x) >> 5;
    float4 b4 = *reinterpret_cast<const float4*>(bias + lane * 4);
    double s0 = 0, s1 = 0, s2 = 0, s3 = 0, q0 = 0, q1 = 0, q2 = 0, q3 = 0;
    for (int n = warp; n < NN; n += nw) {
        float di = g_dinv[n];
        size_t rb = (size_t)n * HH + lane * 4;
        float4 hv = *reinterpret_cast<const float4*>(g_h + rb);
        float sl = di * di;
        float ax = hv.x * sl, ay = hv.y * sl, az = hv.z * sl, aw = hv.w * sl;
        int e0 = g_rowptr[n], e1 = g_rowptr[n + 1];
        #pragma unroll 4
        for (int e = e0; e < e1; e++) {
            int sI = g_ecol[e];
            float nrm = g_dinv[sI] * di;
            float4 v = *reinterpret_cast<const float4*>(g_h + (size_t)sI * HH + lane * 4);
            ax += v.x * nrm; ay += v.y * nrm; az += v.z * nrm; aw += v.w * nrm;
        }
        float4 xv = *reinterpret_cast<const float4*>(g_x + rb);
        float t0 = ax + b4.x + xv.x;
        float t1 = ay + b4.y + xv.y;
        float t2 = az + b4.z + xv.z;
        float t3 = aw + b4.w + xv.w;
        *reinterpret_cast<float4*>(g_x + rb) = make_float4(t0, t1, t2, t3);
        s0 += t0; s1 += t1; s2 += t2; s3 += t3;
        q0 += (double)t0 * t0; q1 += (double)t1 * t1;
        q2 += (double)t2 * t2; q3 += (double)t3 * t3;
    }
    atomicAdd(&g_sum[lane * 4 + 0], s0); atomicAdd(&g_sumsq[lane * 4 + 0], q0);
    atomicAdd(&g_sum[lane * 4 + 1], s1); atomicAdd(&g_sumsq[lane * 4 + 1], q1);
    atomicAdd(&g_sum[lane * 4 + 2], s2); atomicAdd(&g_sumsq[lane * 4 + 2], q2);
    atomicAdd(&g_sum[lane * 4 + 3], s3); atomicAdd(&g_sumsq[lane * 4 + 3], q3);
}
__global__ void bn_final_k(const float* __restrict__ gam, const float* __restrict__ bet) {
    int f = threadIdx.x;
    double mean = g_sum[f] / (double)NN;
    double var  = g_sumsq[f] / (double)NN - mean * mean;
    float a = gam[f] * rsqrtf((float)var + EPSV);
    g_bnA[f] = a;
    g_bnC[f] = bet[f] - (float)mean * a;
}
__global__ void bn_apply_split_k() {
    int idx = blockIdx.x * blockDim.x + threadIdx.x;
    if (blockIdx.x == 0) {
        for (int p = threadIdx.x; p < GG * HH; p += 256) g_pool[p] = 0.0f;
    }
    if (idx < NN * HH) {
        int f = idx & 127;
        float v = g_x[idx] * g_bnA[f] + g_bnC[f];
        g_x[idx] = v;
        __half h = __float2half_rn(v);
        g_ahi[idx] = h;
        g_alo[idx] = __float2half_rn(v - __half2float(h));
    }
}

// ---------------- pooling + fused vn-MLP ----------------
#define PROWS 128
__global__ void pool_k(const float* __restrict__ X, const int* __restrict__ batch) {
    int f = threadIdx.x;
    int r0 = blockIdx.x * PROWS;
    int r1 = min(r0 + PROWS, NN);
    float acc = 0.0f;
    int cur = batch[r0];
    for (int r = r0; r < r1; r++) {
        int gidx = batch[r];
        if (gidx != cur) {
            atomicAdd(&g_pool[cur * HH + f], acc);
            acc = 0.0f; cur = gidx;
        }
        acc += X[(size_t)r * HH + f];
    }
    atomicAdd(&g_pool[cur * HH + f], acc);
}
__global__ void vn_mlp1_k(const float* __restrict__ W1, const float* __restrict__ b1,
                          const float* __restrict__ g1, const float* __restrict__ be1) {
    int f = blockIdx.x;
    int g = threadIdx.x;
    float ic = 1.0f / fmaxf(g_cnt[g], 1.0f);
    float acc = b1[f];
    #pragma unroll 4
    for (int k = 0; k < HH; k++) {
        float vnk = g_vn[g * HH + k] + g_pool[g * HH + k] * ic;
        acc += vnk * W1[k * H2 + f];
    }
    __shared__ float sh[64], sh2[64];
    sh[g] = acc; sh2[g] = acc * acc;
    __syncthreads();
    for (int o = 32; o > 0; o >>= 1) {
        if (g < o) { sh[g] += sh[g + o]; sh2[g] += sh2[g + o]; }
        __syncthreads();
    }
    float mean = sh[0] * (1.0f / 64.0f);
    float var  = sh2[0] * (1.0f / 64.0f) - mean * mean;
    float a = g1[f] * rsqrtf(var + EPSV);
    float c = be1[f] - mean * a;
    g_vnh[g * H2 + f] = gelu_f(acc * a + c);
}
__global__ void vn_mlp2_k(const float* __restrict__ W2, const float* __restrict__ b2,
                          const float* __restrict__ g2, const float* __restrict__ be2) {
    int f = blockIdx.x;
    int g = threadIdx.x;
    float acc = b2[f];
    #pragma unroll 4
    for (int k = 0; k < H2; k++)
        acc += g_vnh[g * H2 + k] * W2[k * HH + f];
    __shared__ float sh[64], sh2[64];
    sh[g] = acc; sh2[g] = acc * acc;
    __syncthreads();
    for (int o = 32; o > 0; o >>= 1) {
        if (g < o) { sh[g] += sh[g + o]; sh2[g] += sh2[g + o]; }
        __syncthreads();
    }
    float mean = sh[0] * (1.0f / 64.0f);
    float var  = sh2[0] * (1.0f / 64.0f) - mean * mean;
    float a = g2[f] * rsqrtf(var + EPSV);
    float c = be2[f] - mean * a;
    g_vn[g * HH + f] = gelu_f(acc * a + c);
}

// ---------------- host ----------------
extern "C" void kernel_launch(void* const* d_in, const int* in_sizes, int n_in,
                              void* d_out, int out_size)
{
    const float* x_in   = (const float*)d_in[0];
    const int*   ei     = (const int*)  d_in[1];
    const int*   batch  = (const int*)  d_in[2];
    const float* pre_W1 = (const float*)d_in[3];
    const float* pre_b1 = (const float*)d_in[4];
    const float* pre_W2 = (const float*)d_in[5];
    const float* pre_b2 = (const float*)d_in[6];
    const float* conv_W = (const float*)d_in[7];
    const float* conv_b = (const float*)d_in[8];
    const float* bn_g   = (const float*)d_in[9];
    const float* bn_b   = (const float*)d_in[10];
    const float* ffn_W1 = (const float*)d_in[11];
    const float* ffn_b1 = (const float*)d_in[12];
    const float* ffn_W2 = (const float*)d_in[13];
    const float* ffn_b2 = (const float*)d_in[14];
    const float* vn_W1  = (const float*)d_in[15];
    const float* vn_b1  = (const float*)d_in[16];
    const float* vn_g1  = (const float*)d_in[17];
    const float* vn_be1 = (const float*)d_in[18];
    const float* vn_W2  = (const float*)d_in[19];
    const float* vn_b2  = (const float*)d_in[20];
    const float* vn_g2  = (const float*)d_in[21];
    const float* vn_be2 = (const float*)d_in[22];
    const float* vn_emb = (const float*)d_in[23];
    const float* post_W1= (const float*)d_in[24];
    const float* post_b1= (const float*)d_in[25];
    const float* post_W2= (const float*)d_in[26];
    const float* post_b2= (const float*)d_in[27];
    float* out = (float*)d_out;

    const int* src = ei;
    const int* dst = ei + NE;

    float *px, *ph, *ppool, *pvnh;
    __half *pahi, *palo, *phhi, *phlo, *pwh;
    cudaGetSymbolAddress((void**)&px,   g_x);
    cudaGetSymbolAddress((void**)&ph,   g_h);
    cudaGetSymbolAddress((void**)&ppool,g_pool);
    cudaGetSymbolAddress((void**)&pvnh, g_vnh);
    cudaGetSymbolAddress((void**)&pahi, g_ahi);
    cudaGetSymbolAddress((void**)&palo, g_alo);
    cudaGetSymbolAddress((void**)&phhi, g_hhi);
    cudaGetSymbolAddress((void**)&phlo, g_hlo);
    cudaGetSymbolAddress((void**)&pwh,  g_wh);

    cudaFuncSetAttribute(mma_gemm<27>, cudaFuncAttributeMaxDynamicSharedMemorySize, GSMEM);
    cudaFuncSetAttribute(mma_gemm<3>,  cudaFuncAttributeMaxDynamicSharedMemorySize, GSMEM);
    cudaFuncSetAttribute(mma_gemm<0>,  cudaFuncAttributeMaxDynamicSharedMemorySize, GSMEM);
    cudaFuncSetAttribute(mma_gemm<7>,  cudaFuncAttributeMaxDynamicSharedMemorySize, GSMEM);

    const int EW = NN * HH;
    dim3 blk(256);
    int gEW = (EW + 255) / 256;
    const int MT = (NN + 127) / 128;   // 782
    const int NB = (NN + 255) / 256;   // 391

    // launches 1-3, then #4 = mma_gemm<27>  (harness adds 2 hidden launches; ncu -s 5 -> #6 overall)
    wprep_all_k<<<(WTOT + 255) / 256, blk>>>(pre_W1, pre_W2, conv_W, ffn_W1, ffn_W2); // 1
    split_k<<<gEW, blk>>>(x_in, pahi, palo, EW);                                      // 2
    deg_init_k<<<NB, blk>>>();                                                        // 3
    mma_gemm<27><<<dim3(2, MT), 256, GSMEM>>>(pahi, palo, pwh + OW_PRE1,
        pre_b1, nullptr, nullptr, phhi, phlo, NN, HH, H2);                            // 4 <- ncu
    deg_edge_k<<<(NE + 255) / 256, blk>>>(dst);
    dinv_cnt_k<<<NB, blk>>>(batch);
    scan1_k<<<NB, blk>>>();
    scan2_k<<<1, 512>>>(NB);
    scan3_k<<<NB, blk>>>();
    scatter_k<<<(NE + 255) / 256, blk>>>(src, dst);
    mma_gemm<3><<<dim3(1, MT), 256, GSMEM>>>(phhi, phlo, pwh + OW_PRE2,
        pre_b2, nullptr, px, nullptr, nullptr, NN, H2, HH);
    vn_init_k<<<(GG * HH + 255) / 256, blk>>>(vn_emb);

    for (int i = 0; i < NHOPS; i++) {
        addvn_split_k<<<gEW, blk>>>(batch);
        mma_gemm<0><<<dim3(1, MT), 256, GSMEM>>>(pahi, palo, pwh + OW_CONV(i),
            nullptr, nullptr, ph, nullptr, nullptr, NN, HH, HH);
        gcn_gather_bn_k<<<256, 256>>>(conv_b + (size_t)i * HH);
        bn_final_k<<<1, HH>>>(bn_g + (size_t)i * HH, bn_b + (size_t)i * HH);
        bn_apply_split_k<<<gEW, blk>>>();
        mma_gemm<27><<<dim3(2, MT), 256, GSMEM>>>(pahi, palo, pwh + OW_FFN1(i),
            ffn_b1 + (size_t)i * H2, nullptr, nullptr, phhi, phlo, NN, HH, H2);
        mma_gemm<7><<<dim3(1, MT), 256, GSMEM>>>(phhi, phlo, pwh + OW_FFN2(i),
            ffn_b2 + (size_t)i * HH, px, px, nullptr, nullptr, NN, H2, HH);
        if (i < NHOPS - 1) {
            pool_k<<<(NN + PROWS - 1) / PROWS, HH>>>(px, batch);
            vn_mlp1_k<<<H2, GG>>>(vn_W1 + (size_t)i * HH * H2, vn_b1 + (size_t)i * H2,
                                  vn_g1 + (size_t)i * H2, vn_be1 + (size_t)i * H2);
            vn_mlp2_k<<<HH, GG>>>(vn_W2 + (size_t)i * H2 * HH, vn_b2 + (size_t)i * HH,
                                  vn_g2 + (size_t)i * HH, vn_be2 + (size_t)i * HH);
        }
    }

    // ---- final pool + post-FFNN ----
    pool_k<<<(NN + PROWS - 1) / PROWS, HH>>>(px, batch);
    dim3 gp1(H2 / 64, 1);
    gemm64<3><<<gp1, blk>>>(ppool, post_W1, post_b1, nullptr, pvnh, GG, HH, H2);
    dim3 gp2(HH / 64, 1);
    gemm64<3><<<gp2, blk>>>(pvnh, post_W2, post_b2, nullptr, out, GG, H2, HH);
}